// round 3
// baseline (speedup 1.0000x reference)
#include <cuda_runtime.h>
#include <cstdint>
#include <math.h>

#define T_LEN 2048
#define BATCH 32
#define DIN   256
#define HID   256
#define NG    1024   // 4*HID
#define AOUT  18
#define GBLK  128    // recurrent CTAs; all co-resident on 148 SMs

typedef unsigned long long ull;

// ---------------- device scratch (no allocs allowed) ----------------
__device__ float g_Gx[(size_t)T_LEN * NG * BATCH];   // [t][n][b]  (256 MiB)
__device__ float g_hT[2][HID * BATCH];               // double-buffered h, [n*32+b]
// two-level barrier: 8 leaf counters (128B apart) + root + generation
__device__ unsigned g_leafc[8][32];
__device__ unsigned g_rootc;
__device__ unsigned g_bar_gen;

// packed f32x2 FMA (SASS FFMA2): 2 fp32 FMAs per instruction
__device__ __forceinline__ ull fma2(ull a, ull b, ull c) {
    ull d;
    asm("fma.rn.f32x2 %0, %1, %2, %3;" : "=l"(d) : "l"(a), "l"(b), "l"(c));
    return d;
}

__device__ __forceinline__ float sigm(float z) {
    return 1.f / (1.f + __expf(-z));
}
__device__ __forceinline__ float tanh_e(float z) {
    // tanh via __expf: rel err ~1e-6, avoids libm tanhf path
    return 2.f / (1.f + __expf(-2.f * z)) - 1.f;
}

// Tree barrier arrival (call from ONE thread per CTA). 16 CTAs per leaf,
// 8 leaves to root. Release semantics on the atomics order prior global
// writes (combined with the preceding intra-CTA barrier). The completer
// publishes `gen_write`. Counters self-reset each generation, so state is
// clean across graph replays; g_bar_gen only ever grows (compared by ==).
__device__ __forceinline__ void bar_arrive(int g, unsigned gen_write) {
    unsigned* leaf = &g_leafc[g & 7][0];
    unsigned old;
    asm volatile("atom.add.release.gpu.global.u32 %0, [%1], 1;"
                 : "=r"(old) : "l"(leaf) : "memory");
    if (old == 15u) {
        asm volatile("st.global.u32 [%0], 0;" :: "l"(leaf) : "memory");
        unsigned o2;
        asm volatile("atom.add.release.gpu.global.u32 %0, [%1], 1;"
                     : "=r"(o2) : "l"(&g_rootc) : "memory");
        if (o2 == 7u) {
            asm volatile("st.global.u32 [%0], 0;" :: "l"(&g_rootc) : "memory");
            asm volatile("st.release.gpu.global.u32 [%0], %1;"
                         :: "l"(&g_bar_gen), "r"(gen_write) : "memory");
        }
    }
}

__device__ __forceinline__ void bar_wait(unsigned target) {
    unsigned v;
    do {
        asm volatile("ld.acquire.gpu.global.u32 %0, [%1];"
                     : "=r"(v) : "l"(&g_bar_gen) : "memory");
    } while (v != target);
}

// =====================================================================
// Phase 1: Gx[t][n][b] = (x@W[0:256,:])[r=t*32+b, n] + bias[n]
// (unchanged from R1 — control; gemm work continues after recurrence fix)
// =====================================================================
__global__ void __launch_bounds__(256) gemm_x(const float* __restrict__ x,
                                              const float* __restrict__ W,
                                              const float* __restrict__ bias) {
    __shared__ float As[16 * 128];   // [k][m]
    __shared__ float Bsd[16 * 128];  // [k][n duplicated x2]

    int tid = threadIdx.x;
    int mt = tid & 15, nt = tid >> 4;
    int rbase = blockIdx.y * 128;
    int nb = blockIdx.x * 64;

    ull acc[4][4];
#pragma unroll
    for (int i = 0; i < 4; ++i)
#pragma unroll
        for (int j = 0; j < 4; ++j) acc[i][j] = 0ull;

    for (int kt = 0; kt < 16; ++kt) {
        {   // stage X tile: 128 rows x 16 k
            int row = tid >> 1, half = tid & 1;
            int r = rbase + row;
            int b = r & 31, t = r >> 5;
            const float* xp = x + ((size_t)b * T_LEN + t) * DIN + kt * 16 + half * 8;
            float4 v0 = *(const float4*)xp;
            float4 v1 = *(const float4*)(xp + 4);
            int ko = half * 8;
            As[(ko + 0) * 128 + row] = v0.x;
            As[(ko + 1) * 128 + row] = v0.y;
            As[(ko + 2) * 128 + row] = v0.z;
            As[(ko + 3) * 128 + row] = v0.w;
            As[(ko + 4) * 128 + row] = v1.x;
            As[(ko + 5) * 128 + row] = v1.y;
            As[(ko + 6) * 128 + row] = v1.z;
            As[(ko + 7) * 128 + row] = v1.w;
        }
        {   // stage W tile duplicated: 16 k x 64 n
            int k = tid >> 4;
            int nn = (tid & 15) * 4;
            float4 wv = *(const float4*)(W + (size_t)(kt * 16 + k) * NG + nb + nn);
            float4 d0 = make_float4(wv.x, wv.x, wv.y, wv.y);
            float4 d1 = make_float4(wv.z, wv.z, wv.w, wv.w);
            *(float4*)&Bsd[k * 128 + nn * 2]     = d0;
            *(float4*)&Bsd[k * 128 + nn * 2 + 4] = d1;
        }
        __syncthreads();
#pragma unroll
        for (int k = 0; k < 16; ++k) {
            ulonglong2 a01 = *(const ulonglong2*)&As[k * 128 + mt * 8];
            ulonglong2 a23 = *(const ulonglong2*)&As[k * 128 + mt * 8 + 4];
            ulonglong2 b01 = *(const ulonglong2*)&Bsd[k * 128 + nt * 8];
            ulonglong2 b23 = *(const ulonglong2*)&Bsd[k * 128 + nt * 8 + 4];
            ull am[4] = {a01.x, a01.y, a23.x, a23.y};
            ull bd[4] = {b01.x, b01.y, b23.x, b23.y};
#pragma unroll
            for (int mp = 0; mp < 4; ++mp)
#pragma unroll
                for (int nn = 0; nn < 4; ++nn)
                    acc[mp][nn] = fma2(am[mp], bd[nn], acc[mp][nn]);
        }
        __syncthreads();
    }
#pragma unroll
    for (int mp = 0; mp < 4; ++mp) {
        int m = mt * 8 + mp * 2;
        int r = rbase + m;
        int b = r & 31, t = r >> 5;
#pragma unroll
        for (int nn = 0; nn < 4; ++nn) {
            int n = nb + nt * 4 + nn;
            float bv = __ldg(bias + n);
            float2 v = *(float2*)&acc[mp][nn];
            v.x += bv; v.y += bv;
            *(float2*)&g_Gx[((size_t)t * NG + n) * BATCH + b] = v;
        }
    }
}

// =====================================================================
// Phase 2: persistent recurrence. CTA g owns h-cols {2g,2g+1} -> 8 gate cols.
// Arrive-early / wait-late tree barrier; outLL store + Gx prefetch hidden
// behind other CTAs' barrier latency.
// =====================================================================
__global__ void __launch_bounds__(256) lstm_rec(const float* __restrict__ W,
                                                const int* __restrict__ seq_lens,
                                                const float* __restrict__ c_in,
                                                const float* __restrict__ h_in,
                                                float* __restrict__ out) {
    extern __shared__ float sm[];
    float* ws   = sm;                   // 4096 f: dup weights [k][16]
    float* hs   = sm + 4096;            // 8192 f: h [k][b]
    ull*   ps2  = (ull*)(sm + 12288);   // 1152 ull: partials, pad 9
    float* gred = sm + 14592;           // 256 f: reduced gates [col][b]

    int tid = threadIdx.x;
    int g = blockIdx.x;
    int n0 = g * 2;

    {   // preload duplicated recurrent weights (constant across steps)
        int k = tid;
#pragma unroll
        for (int c8 = 0; c8 < 8; ++c8) {
            int gcol = (c8 >> 1) * HID + n0 + (c8 & 1);
            float wv = W[(size_t)(DIN + k) * NG + gcol];
            ws[k * 16 + c8 * 2]     = wv;
            ws[k * 16 + c8 * 2 + 1] = wv;
        }
    }

    int cc = tid >> 5;      // for tid<64: local h-col 0/1
    int bb = tid & 31;      // batch
    float creg = 0.f, hreg = 0.f;
    int slen = 0;
    if (tid < 64) {
        int n = n0 + cc;
        creg = c_in[bb * HID + n];
        hreg = h_in[bb * HID + n];
        slen = seq_lens[bb];
        g_hT[0][n * BATCH + bb] = hreg;
    }
    __syncthreads();

    unsigned gen0 = 0;
    if (tid == 0) {
        asm volatile("ld.volatile.global.u32 %0, [%1];"
                     : "=r"(gen0) : "l"(&g_bar_gen));
        bar_arrive(g, gen0 + 1);   // publish h(0)
    }

    int lane = tid & 31, wrp = tid >> 5;
    int p = lane & 15, cg = lane >> 4;
    int kbase = wrp * 32;
    float* outLL = out + (size_t)BATCH * T_LEN * AOUT;
    const float* gxbase = (tid < 64) ? (g_Gx + ((size_t)(n0 + cc)) * BATCH + bb) : g_Gx;

    // prefetch Gx(0)
    float gx0 = 0.f, gx1 = 0.f, gx2 = 0.f, gx3 = 0.f;
    if (tid < 64) {
        const float* gp = gxbase;   // t = 0
        gx0 = gp[0];
        gx1 = gp[(size_t)256 * BATCH];
        gx2 = gp[(size_t)512 * BATCH];
        gx3 = gp[(size_t)768 * BATCH];
    }

#pragma unroll 1
    for (int t = 0; t < T_LEN; ++t) {
        if (tid == 0) bar_wait(gen0 + 1u + (unsigned)t);
        __syncthreads();
        int buf = t & 1;

        // stage full h [256x32] from L2 into smem
        const float* hg = g_hT[buf];
#pragma unroll
        for (int j2 = 0; j2 < 8; ++j2) {
            int idx = j2 * 1024 + tid * 4;
            *(float4*)&hs[idx] = *(const float4*)&hg[idx];
        }
        __syncthreads();

        // h @ Wh slice: 32 k's per warp, 4 cols x 2 batches per lane
        ull a0 = 0, a1 = 0, a2 = 0, a3 = 0;
#pragma unroll
        for (int kk = 0; kk < 32; ++kk) {
            int k = kbase + kk;
            ull h2 = *(const ull*)&hs[k * 32 + p * 2];
            ulonglong2 wa = *(const ulonglong2*)&ws[k * 16 + cg * 8];
            ulonglong2 wb = *(const ulonglong2*)&ws[k * 16 + cg * 8 + 4];
            a0 = fma2(h2, wa.x, a0);
            a1 = fma2(h2, wa.y, a1);
            a2 = fma2(h2, wb.x, a2);
            a3 = fma2(h2, wb.y, a3);
        }
        int cb = cg * 4;
        ps2[((cb + 0) * 16 + p) * 9 + wrp] = a0;
        ps2[((cb + 1) * 16 + p) * 9 + wrp] = a1;
        ps2[((cb + 2) * 16 + p) * 9 + wrp] = a2;
        ps2[((cb + 3) * 16 + p) * 9 + wrp] = a3;
        __syncthreads();

        if (tid < 128) {   // cross-warp k-reduction
            int col = tid >> 4, pp = tid & 15;
            const ull* base = ps2 + ((size_t)col * 16 + pp) * 9;
            float sx = 0.f, sy = 0.f;
#pragma unroll
            for (int w2 = 0; w2 < 8; ++w2) {
                float2 f = *(const float2*)&base[w2];
                sx += f.x; sy += f.y;
            }
            gred[col * 32 + pp * 2]     = sx;
            gred[col * 32 + pp * 2 + 1] = sy;
        }
        __syncthreads();

        float outv = 0.f;
        if (tid < 64) {    // activations + state update
            int n = n0 + cc;
            float gi = gred[(0 * 2 + cc) * 32 + bb] + gx0;
            float gj = gred[(1 * 2 + cc) * 32 + bb] + gx1;
            float gf = gred[(2 * 2 + cc) * 32 + bb] + gx2;
            float go = gred[(3 * 2 + cc) * 32 + bb] + gx3;
            float sf = sigm(gf + 1.f);   // FORGET_BIAS = 1
            float si = sigm(gi);
            float so = sigm(go);
            float nc = creg * sf + si * tanh_e(gj);
            float nh = tanh_e(nc) * so;
            bool mvalid = (t < slen);
            if (mvalid) { creg = nc; hreg = nh; }
            outv = mvalid ? nh : 0.f;
            g_hT[buf ^ 1][n * BATCH + bb] = hreg;   // publish h(t+1)

            // gate the arrive on the 64 publishing threads only
            asm volatile("bar.sync 1, 64;" ::: "memory");
            if (tid == 0 && t + 1 < T_LEN)
                bar_arrive(g, gen0 + 2u + (unsigned)t);

            // hidden behind other CTAs' barrier latency:
            outLL[((size_t)bb * T_LEN + t) * HID + n] = outv;
            int tn = (t + 1 < T_LEN) ? (t + 1) : t;   // clamp (last reload harmless)
            const float* gp = gxbase + (size_t)tn * NG * BATCH;
            gx0 = gp[0];
            gx1 = gp[(size_t)256 * BATCH];
            gx2 = gp[(size_t)512 * BATCH];
            gx3 = gp[(size_t)768 * BATCH];
        }
    }

    if (tid < 64) {   // finals
        int n = n0 + cc;
        float* cf = out + (size_t)BATCH * T_LEN * AOUT + (size_t)BATCH * T_LEN * HID;
        float* hf = cf + BATCH * HID;
        cf[bb * HID + n] = creg;
        hf[bb * HID + n] = hreg;
    }
}

// =====================================================================
// Phase 3: logits = last_layer @ W_out + b_out.  288 = 16 rows x 18 cols.
// =====================================================================
#define PROJ_TPB 288
__global__ void __launch_bounds__(PROJ_TPB) proj_kernel(const float* __restrict__ LL,
                                                        const float* __restrict__ Wo,
                                                        const float* __restrict__ bo,
                                                        float* __restrict__ logits,
                                                        int tiles_per_block) {
    __shared__ float Wsm[256 * 18];
    __shared__ float Lsm[16 * 257];

    int tid = threadIdx.x;
    for (int i = tid; i < 256 * 18; i += PROJ_TPB) Wsm[i] = Wo[i];
    int r = tid / 18;
    int a = tid - r * 18;
    float bv = bo[a];

    for (int tile = 0; tile < tiles_per_block; ++tile) {
        int rbase = (blockIdx.x * tiles_per_block + tile) * 16;
        __syncthreads();
        for (int i = tid; i < 16 * 256; i += PROJ_TPB) {
            int rr = i >> 8, c = i & 255;
            Lsm[rr * 257 + c] = LL[(size_t)rbase * 256 + i];
        }
        __syncthreads();
        float acc = 0.f;
        const float* lr = &Lsm[r * 257];
#pragma unroll 8
        for (int h = 0; h < 256; ++h)
            acc = fmaf(lr[h], Wsm[h * 18 + a], acc);
        logits[(size_t)(rbase + r) * AOUT + a] = acc + bv;
    }
}

// =====================================================================
extern "C" void kernel_launch(void* const* d_in, const int* in_sizes, int n_in,
                              void* d_out, int out_size) {
    const float* x        = (const float*)d_in[0];
    const int*   seq_lens = (const int*)  d_in[1];
    const float* c_in     = (const float*)d_in[2];
    const float* h_in     = (const float*)d_in[3];
    const float* W        = (const float*)d_in[4];
    const float* b        = (const float*)d_in[5];
    const float* W_out    = (const float*)d_in[6];
    const float* b_out    = (const float*)d_in[7];
    float* out = (float*)d_out;

    cudaFuncSetAttribute(lstm_rec, cudaFuncAttributeMaxDynamicSharedMemorySize, 59392);

    // Phase 1: input GEMM for all timesteps
    gemm_x<<<dim3(16, 512), 256>>>(x, W, b);

    // Phase 2: persistent recurrence (writes last_layer, c_fin, h_fin)
    lstm_rec<<<GBLK, 256, 59392>>>(W, seq_lens, c_in, h_in, out);

    // Phase 3: output projection (reads last_layer from out)
    const float* LL = out + (size_t)BATCH * T_LEN * AOUT;
    proj_kernel<<<512, PROJ_TPB>>>(LL, W_out, b_out, out, 8);
}

// round 5
// speedup vs baseline: 1.0984x; 1.0984x over previous
#include <cuda_runtime.h>
#include <cstdint>
#include <math.h>

#define T_LEN 2048
#define BATCH 32
#define DIN   256
#define HID   256
#define NG    1024   // 4*HID
#define AOUT  18
#define GBLK  128    // recurrent CTAs; all co-resident on 148 SMs

typedef unsigned long long ull;

// ---------------- device scratch (no allocs allowed) ----------------
__device__ float g_Gx[(size_t)T_LEN * NG * BATCH];   // [t][n][b]  (256 MiB)
__device__ float g_hT[2][HID * BATCH];               // double-buffered h, [n*32+b]
__device__ unsigned g_bar_cnt;
__device__ unsigned g_bar_gen;

// packed f32x2 FMA (SASS FFMA2): 2 fp32 FMAs per instruction
__device__ __forceinline__ ull fma2(ull a, ull b, ull c) {
    ull d;
    asm("fma.rn.f32x2 %0, %1, %2, %3;" : "=l"(d) : "l"(a), "l"(b), "l"(c));
    return d;
}

__device__ __forceinline__ float sigm(float z) {
    return 1.f / (1.f + __expf(-z));
}
__device__ __forceinline__ float tanh_e(float z) {
    return 2.f / (1.f + __expf(-2.f * z)) - 1.f;
}

// Flat grid barrier over exactly GBLK co-resident CTAs (R1-proven).
// State self-restores across graph replays.
__device__ __forceinline__ void grid_barrier() {
    __syncthreads();
    if (threadIdx.x == 0) {
        __threadfence();
        unsigned gen = *(volatile unsigned*)&g_bar_gen;
        if (atomicAdd(&g_bar_cnt, 1u) == GBLK - 1u) {
            atomicExch(&g_bar_cnt, 0u);
            __threadfence();
            atomicExch(&g_bar_gen, gen + 1u);
        } else {
            while (*(volatile unsigned*)&g_bar_gen == gen) { }
        }
        __threadfence();
    }
    __syncthreads();
}

// =====================================================================
// Phase 1: Gx[t][n][b] = (x@W[0:256,:])[r=t*32+b, n] + bias[n]
// Double-buffered smem: 1 syncthreads/ktile, LDG(k+1) overlaps FMA(k).
// =====================================================================
__global__ void __launch_bounds__(256) gemm_x(const float* __restrict__ x,
                                              const float* __restrict__ W,
                                              const float* __restrict__ bias) {
    __shared__ float As[2][16 * 128];   // [k][m]
    __shared__ float Bsd[2][16 * 128];  // [k][n duplicated x2]

    int tid = threadIdx.x;
    int mt = tid & 15, nt = tid >> 4;
    int rbase = blockIdx.y * 128;
    int nb = blockIdx.x * 64;

    // staging addresses (fixed per thread)
    int row = tid >> 1, half = tid & 1;
    int rr = rbase + row;
    int bB = rr & 31, tT = rr >> 5;
    const float* xbase = x + ((size_t)bB * T_LEN + tT) * DIN + half * 8;
    int wk = tid >> 4, wn = (tid & 15) * 4;
    const float* wbase = W + (size_t)wk * NG + nb + wn;

    float4 xa, xb, wv;
    ull acc[4][4];
#pragma unroll
    for (int i = 0; i < 4; ++i)
#pragma unroll
        for (int j = 0; j < 4; ++j) acc[i][j] = 0ull;

    // load ktile 0
    xa = *(const float4*)(xbase);
    xb = *(const float4*)(xbase + 4);
    wv = *(const float4*)(wbase);

#define STASH(buf)                                                       \
    {                                                                    \
        float* A = As[buf];                                              \
        int ko = half * 8;                                               \
        A[(ko + 0) * 128 + row] = xa.x; A[(ko + 1) * 128 + row] = xa.y;  \
        A[(ko + 2) * 128 + row] = xa.z; A[(ko + 3) * 128 + row] = xa.w;  \
        A[(ko + 4) * 128 + row] = xb.x; A[(ko + 5) * 128 + row] = xb.y;  \
        A[(ko + 6) * 128 + row] = xb.z; A[(ko + 7) * 128 + row] = xb.w;  \
        float* Bd = Bsd[buf];                                            \
        float4 d0 = make_float4(wv.x, wv.x, wv.y, wv.y);                 \
        float4 d1 = make_float4(wv.z, wv.z, wv.w, wv.w);                 \
        *(float4*)&Bd[wk * 128 + wn * 2]     = d0;                       \
        *(float4*)&Bd[wk * 128 + wn * 2 + 4] = d1;                       \
    }

    STASH(0);
    __syncthreads();

    for (int kt = 0; kt < 16; ++kt) {
        int buf = kt & 1;
        if (kt < 15) {   // prefetch next ktile (overlaps with compute)
            xa = *(const float4*)(xbase + (kt + 1) * 16);
            xb = *(const float4*)(xbase + (kt + 1) * 16 + 4);
            wv = *(const float4*)(wbase + (size_t)(kt + 1) * 16 * NG);
        }
        const float* A = As[buf];
        const float* Bd = Bsd[buf];
#pragma unroll
        for (int k = 0; k < 16; ++k) {
            ulonglong2 a01 = *(const ulonglong2*)&A[k * 128 + mt * 8];
            ulonglong2 a23 = *(const ulonglong2*)&A[k * 128 + mt * 8 + 4];
            ulonglong2 b01 = *(const ulonglong2*)&Bd[k * 128 + nt * 8];
            ulonglong2 b23 = *(const ulonglong2*)&Bd[k * 128 + nt * 8 + 4];
            ull am[4] = {a01.x, a01.y, a23.x, a23.y};
            ull bd[4] = {b01.x, b01.y, b23.x, b23.y};
#pragma unroll
            for (int mp = 0; mp < 4; ++mp)
#pragma unroll
                for (int nn = 0; nn < 4; ++nn)
                    acc[mp][nn] = fma2(am[mp], bd[nn], acc[mp][nn]);
        }
        if (kt < 15) {
            STASH(buf ^ 1);
            __syncthreads();
        }
    }
#undef STASH

#pragma unroll
    for (int mp = 0; mp < 4; ++mp) {
        int m = mt * 8 + mp * 2;
        int r = rbase + m;
        int b = r & 31, t = r >> 5;
#pragma unroll
        for (int nn = 0; nn < 4; ++nn) {
            int n = nb + nt * 4 + nn;
            float bv = __ldg(bias + n);
            float2 v = *(float2*)&acc[mp][nn];
            v.x += bv; v.y += bv;
            *(float2*)&g_Gx[((size_t)t * NG + n) * BATCH + b] = v;
        }
    }
}

// =====================================================================
// Phase 2: persistent recurrence. CTA g owns h-cols {2g,2g+1} -> 8 gate cols.
// New lane map: pg=lane&7 (2 batch-pairs), ch=lane>>3 (2 cols) ->
// one LDS.128 (h) + one LDS.128 (dup w) per 4 FFMA2 (was 3 LDS / 4 FFMA2).
// =====================================================================
__global__ void __launch_bounds__(256) lstm_rec(const float* __restrict__ W,
                                                const int* __restrict__ seq_lens,
                                                const float* __restrict__ c_in,
                                                const float* __restrict__ h_in,
                                                float* __restrict__ out) {
    extern __shared__ float sm[];
    float* ws   = sm;                   // 4096 f: dup weights [k][16]
    float* hs   = sm + 4096;            // 8192 f: h [k][b]
    ull*   ps2  = (ull*)(sm + 12288);   // 1152 ull: partials, pad 9
    float* gred = sm + 14592;           // 256 f: reduced gates [col][b]

    int tid = threadIdx.x;
    int g = blockIdx.x;
    int n0 = g * 2;

    {   // preload duplicated recurrent weights (constant across steps)
        int k = tid;
#pragma unroll
        for (int c8 = 0; c8 < 8; ++c8) {
            int gcol = (c8 >> 1) * HID + n0 + (c8 & 1);
            float wv = W[(size_t)(DIN + k) * NG + gcol];
            ws[k * 16 + c8 * 2]     = wv;
            ws[k * 16 + c8 * 2 + 1] = wv;
        }
    }

    int cc = tid >> 5;      // for tid<64: local h-col 0/1
    int bb = tid & 31;      // batch
    float creg = 0.f, hreg = 0.f;
    int slen = 0;
    if (tid < 64) {
        int n = n0 + cc;
        creg = c_in[bb * HID + n];
        hreg = h_in[bb * HID + n];
        slen = seq_lens[bb];
        g_hT[0][n * BATCH + bb] = hreg;
    }

    int lane = tid & 31, wrp = tid >> 5;
    int pg = lane & 7;      // batch-pairs {2pg, 2pg+1}
    int ch = lane >> 3;     // cols {2ch, 2ch+1}  (ch in [0,4))
    int kbase = wrp * 32;
    float* outLL = out + (size_t)BATCH * T_LEN * AOUT;

#pragma unroll 1
    for (int t = 0; t < T_LEN; ++t) {
        grid_barrier();
        int buf = t & 1;

        // prefetch precomputed input gates ([t][n][b] -> coalesced)
        float gx0 = 0.f, gx1 = 0.f, gx2 = 0.f, gx3 = 0.f;
        if (tid < 64) {
            const float* gp = g_Gx + ((size_t)t * NG + n0 + cc) * BATCH + bb;
            gx0 = gp[0];
            gx1 = gp[(size_t)256 * BATCH];
            gx2 = gp[(size_t)512 * BATCH];
            gx3 = gp[(size_t)768 * BATCH];
        }

        // stage full h [256x32] from L2 into smem
        const float* hg = g_hT[buf];
#pragma unroll
        for (int j2 = 0; j2 < 8; ++j2) {
            int idx = j2 * 1024 + tid * 4;
            *(float4*)&hs[idx] = *(const float4*)&hg[idx];
        }
        __syncthreads();

        // h @ Wh slice: 32 k's per warp, 2 cols x 4 batches per lane
        ull a00 = 0, a01v = 0, a10 = 0, a11 = 0;
#pragma unroll
        for (int kk = 0; kk < 32; ++kk) {
            int k = kbase + kk;
            ulonglong2 h2 = *(const ulonglong2*)&hs[k * 32 + pg * 4];
            ulonglong2 w2 = *(const ulonglong2*)&ws[k * 16 + ch * 4];
            a00  = fma2(h2.x, w2.x, a00);
            a01v = fma2(h2.y, w2.x, a01v);
            a10  = fma2(h2.x, w2.y, a10);
            a11  = fma2(h2.y, w2.y, a11);
        }
        ps2[((2 * ch + 0) * 16 + 2 * pg + 0) * 9 + wrp] = a00;
        ps2[((2 * ch + 0) * 16 + 2 * pg + 1) * 9 + wrp] = a01v;
        ps2[((2 * ch + 1) * 16 + 2 * pg + 0) * 9 + wrp] = a10;
        ps2[((2 * ch + 1) * 16 + 2 * pg + 1) * 9 + wrp] = a11;
        __syncthreads();

        if (tid < 128) {   // cross-warp k-reduction
            int col = tid >> 4, pp = tid & 15;
            const ull* base = ps2 + ((size_t)col * 16 + pp) * 9;
            float sx = 0.f, sy = 0.f;
#pragma unroll
            for (int w2i = 0; w2i < 8; ++w2i) {
                float2 f = *(const float2*)&base[w2i];
                sx += f.x; sy += f.y;
            }
            gred[col * 32 + pp * 2]     = sx;
            gred[col * 32 + pp * 2 + 1] = sy;
        }
        __syncthreads();

        if (tid < 64) {    // activations + state update + outputs
            int n = n0 + cc;
            float gi = gred[(0 * 2 + cc) * 32 + bb] + gx0;
            float gj = gred[(1 * 2 + cc) * 32 + bb] + gx1;
            float gf = gred[(2 * 2 + cc) * 32 + bb] + gx2;
            float go = gred[(3 * 2 + cc) * 32 + bb] + gx3;
            float sf = sigm(gf + 1.f);   // FORGET_BIAS = 1
            float si = sigm(gi);
            float so = sigm(go);
            float nc = creg * sf + si * tanh_e(gj);
            float nh = tanh_e(nc) * so;
            bool mvalid = (t < slen);
            if (mvalid) { creg = nc; hreg = nh; }
            outLL[((size_t)bb * T_LEN + t) * HID + n] = mvalid ? nh : 0.f;
            g_hT[buf ^ 1][n * BATCH + bb] = hreg;
        }
    }

    if (tid < 64) {   // finals
        int n = n0 + cc;
        float* cf = out + (size_t)BATCH * T_LEN * AOUT + (size_t)BATCH * T_LEN * HID;
        float* hf = cf + BATCH * HID;
        cf[bb * HID + n] = creg;
        hf[bb * HID + n] = hreg;
    }
}

// =====================================================================
// Phase 3: logits = last_layer @ W_out + b_out.  288 = 16 rows x 18 cols.
// =====================================================================
#define PROJ_TPB 288
__global__ void __launch_bounds__(PROJ_TPB) proj_kernel(const float* __restrict__ LL,
                                                        const float* __restrict__ Wo,
                                                        const float* __restrict__ bo,
                                                        float* __restrict__ logits,
                                                        int tiles_per_block) {
    __shared__ float Wsm[256 * 18];
    __shared__ float Lsm[16 * 257];

    int tid = threadIdx.x;
    for (int i = tid; i < 256 * 18; i += PROJ_TPB) Wsm[i] = Wo[i];
    int r = tid / 18;
    int a = tid - r * 18;
    float bv = bo[a];

    for (int tile = 0; tile < tiles_per_block; ++tile) {
        int rbase = (blockIdx.x * tiles_per_block + tile) * 16;
        __syncthreads();
        for (int i = tid; i < 16 * 256; i += PROJ_TPB) {
            int rr = i >> 8, c = i & 255;
            Lsm[rr * 257 + c] = LL[(size_t)rbase * 256 + i];
        }
        __syncthreads();
        float acc = 0.f;
        const float* lr = &Lsm[r * 257];
#pragma unroll 8
        for (int h = 0; h < 256; ++h)
            acc = fmaf(lr[h], Wsm[h * 18 + a], acc);
        logits[(size_t)(rbase + r) * AOUT + a] = acc + bv;
    }
}

// =====================================================================
extern "C" void kernel_launch(void* const* d_in, const int* in_sizes, int n_in,
                              void* d_out, int out_size) {
    const float* x        = (const float*)d_in[0];
    const int*   seq_lens = (const int*)  d_in[1];
    const float* c_in     = (const float*)d_in[2];
    const float* h_in     = (const float*)d_in[3];
    const float* W        = (const float*)d_in[4];
    const float* b        = (const float*)d_in[5];
    const float* W_out    = (const float*)d_in[6];
    const float* b_out    = (const float*)d_in[7];
    float* out = (float*)d_out;

    cudaFuncSetAttribute(lstm_rec, cudaFuncAttributeMaxDynamicSharedMemorySize, 59392);

    // Phase 1: input GEMM for all timesteps
    gemm_x<<<dim3(16, 512), 256>>>(x, W, b);

    // Phase 2: persistent recurrence (writes last_layer, c_fin, h_fin)
    lstm_rec<<<GBLK, 256, 59392>>>(W, seq_lens, c_in, h_in, out);

    // Phase 3: output projection (reads last_layer from out)
    const float* LL = out + (size_t)BATCH * T_LEN * AOUT;
    proj_kernel<<<512, PROJ_TPB>>>(LL, W_out, b_out, out, 8);
}

// round 9
// speedup vs baseline: 1.3809x; 1.2573x over previous
#include <cuda_runtime.h>
#include <cstdint>
#include <math.h>

#define T_LEN 2048
#define BATCH 32
#define DIN   256
#define HID   256
#define NG    1024   // 4*HID
#define AOUT  18
#define CLC   8      // CTAs per cluster
#define GBLK  128    // 16 clusters x 8 CTAs

typedef unsigned long long ull;

// ---------------- device scratch (no allocs allowed) ----------------
__device__ float g_Gx[(size_t)T_LEN * BATCH * NG];   // [r = t*32+b][n]  (256 MiB)

// packed f32x2 FMA (SASS FFMA2): 2 fp32 FMAs per instruction
__device__ __forceinline__ ull fma2(ull a, ull b, ull c) {
    ull d;
    asm("fma.rn.f32x2 %0, %1, %2, %3;" : "=l"(d) : "l"(a), "l"(b), "l"(c));
    return d;
}
__device__ __forceinline__ ull dupf(float v) {
    unsigned u = __float_as_uint(v);
    return (ull)u | ((ull)u << 32);
}
__device__ __forceinline__ float sigm(float z) { return 1.f / (1.f + __expf(-z)); }
__device__ __forceinline__ float tanh_e(float z) { return 2.f / (1.f + __expf(-2.f * z)) - 1.f; }

__device__ __forceinline__ unsigned smem_u32(const void* p) {
    unsigned a;
    asm("{ .reg .u64 t; cvta.to.shared.u64 t, %1; cvt.u32.u64 %0, t; }"
        : "=r"(a) : "l"(p));
    return a;
}

// =====================================================================
// Phase 1: Gx[r][n] = (x@W[0:256,:])[r, n] + bias[n],  r = t*32 + b
// Double-buffered smem, f32x2 register tiling (from R3).
// =====================================================================
__global__ void __launch_bounds__(256) gemm_x(const float* __restrict__ x,
                                              const float* __restrict__ W,
                                              const float* __restrict__ bias) {
    __shared__ float As[2][16 * 128];
    __shared__ float Bsd[2][16 * 128];

    int tid = threadIdx.x;
    int mt = tid & 15, nt = tid >> 4;
    int rbase = blockIdx.y * 128;
    int nb = blockIdx.x * 64;

    int row = tid >> 1, half = tid & 1;
    int rr = rbase + row;
    int bB = rr & 31, tT = rr >> 5;
    const float* xbase = x + ((size_t)bB * T_LEN + tT) * DIN + half * 8;
    int wk = tid >> 4, wn = (tid & 15) * 4;
    const float* wbase = W + (size_t)wk * NG + nb + wn;

    float4 xa, xb, wv;
    ull acc[4][4];
#pragma unroll
    for (int i = 0; i < 4; ++i)
#pragma unroll
        for (int j = 0; j < 4; ++j) acc[i][j] = 0ull;

    xa = *(const float4*)(xbase);
    xb = *(const float4*)(xbase + 4);
    wv = *(const float4*)(wbase);

#define STASH(buf)                                                       \
    {                                                                    \
        float* A = As[buf];                                              \
        int ko = half * 8;                                               \
        A[(ko + 0) * 128 + row] = xa.x; A[(ko + 1) * 128 + row] = xa.y;  \
        A[(ko + 2) * 128 + row] = xa.z; A[(ko + 3) * 128 + row] = xa.w;  \
        A[(ko + 4) * 128 + row] = xb.x; A[(ko + 5) * 128 + row] = xb.y;  \
        A[(ko + 6) * 128 + row] = xb.z; A[(ko + 7) * 128 + row] = xb.w;  \
        float* Bd = Bsd[buf];                                            \
        float4 d0 = make_float4(wv.x, wv.x, wv.y, wv.y);                 \
        float4 d1 = make_float4(wv.z, wv.z, wv.w, wv.w);                 \
        *(float4*)&Bd[wk * 128 + wn * 2]     = d0;                       \
        *(float4*)&Bd[wk * 128 + wn * 2 + 4] = d1;                       \
    }

    STASH(0);
    __syncthreads();

    for (int kt = 0; kt < 16; ++kt) {
        int buf = kt & 1;
        if (kt < 15) {
            xa = *(const float4*)(xbase + (kt + 1) * 16);
            xb = *(const float4*)(xbase + (kt + 1) * 16 + 4);
            wv = *(const float4*)(wbase + (size_t)(kt + 1) * 16 * NG);
        }
        const float* A = As[buf];
        const float* Bd = Bsd[buf];
#pragma unroll
        for (int k = 0; k < 16; ++k) {
            ulonglong2 a01 = *(const ulonglong2*)&A[k * 128 + mt * 8];
            ulonglong2 a23 = *(const ulonglong2*)&A[k * 128 + mt * 8 + 4];
            ulonglong2 b01 = *(const ulonglong2*)&Bd[k * 128 + nt * 8];
            ulonglong2 b23 = *(const ulonglong2*)&Bd[k * 128 + nt * 8 + 4];
            ull am[4] = {a01.x, a01.y, a23.x, a23.y};
            ull bd[4] = {b01.x, b01.y, b23.x, b23.y};
#pragma unroll
            for (int mp = 0; mp < 4; ++mp)
#pragma unroll
                for (int nn = 0; nn < 4; ++nn)
                    acc[mp][nn] = fma2(am[mp], bd[nn], acc[mp][nn]);
        }
        if (kt < 15) {
            STASH(buf ^ 1);
            __syncthreads();
        }
    }
#undef STASH

    // epilogue: row-major [r][n], float4 per row
    float4 bv = *(const float4*)&bias[nb + nt * 4];
#pragma unroll
    for (int mp = 0; mp < 4; ++mp) {
        int r = rbase + mt * 8 + mp * 2;
        float2 v0 = *(float2*)&acc[mp][0];
        float2 v1 = *(float2*)&acc[mp][1];
        float2 v2 = *(float2*)&acc[mp][2];
        float2 v3 = *(float2*)&acc[mp][3];
        float4 o0 = make_float4(v0.x + bv.x, v1.x + bv.y, v2.x + bv.z, v3.x + bv.w);
        float4 o1 = make_float4(v0.y + bv.x, v1.y + bv.y, v2.y + bv.z, v3.y + bv.w);
        *(float4*)&g_Gx[(size_t)r * NG + nb + nt * 4]       = o0;
        *(float4*)&g_Gx[(size_t)(r + 1) * NG + nb + nt * 4] = o1;
    }
}

// =====================================================================
// Phase 2: clustered recurrence. Cluster (8 CTAs) owns 2 batches.
// CTA rank owns h-cols [32r, 32r+32) -> 128 gate cols; recurrent weights
// live in REGISTERS (128/thread). h exchanged via DSMEM, sync = cluster
// barrier. No grid-wide sync, no L2 h-broadcast.
// =====================================================================
__global__ void __launch_bounds__(256, 1) __cluster_dims__(CLC, 1, 1)
lstm_rec(const float* __restrict__ W,
         const int* __restrict__ seq_lens,
         const float* __restrict__ c_in,
         const float* __restrict__ h_in,
         float* __restrict__ out) {
    __shared__ __align__(16) ull hsd[2][HID][2];   // duplicated h pairs, 8KB
    __shared__ __align__(16) ull part[8][32][4];   // k-partials, 8KB
    __shared__ float gred[2][128];                 // reduced gates [b][gc]

    int tid = threadIdx.x;
    int lane = tid & 31, wrp = tid >> 5;
    unsigned rank;
    asm("mov.u32 %0, %%cluster_ctarank;" : "=r"(rank));
    int cid = blockIdx.x >> 3;          // cluster id = batch group
    int b0 = cid * 2;

    // ---- weight-stationary registers: 32 k x 4 gate cols per thread ----
    ull wreg[32][2];
    {
        int gc4 = lane * 4;
        int n = (gc4 >> 5) * 256 + (int)rank * 32 + (gc4 & 31);
#pragma unroll
        for (int kk = 0; kk < 32; ++kk) {
            int k = wrp * 32 + kk;
            float4 w4 = *(const float4*)&W[(size_t)(DIN + k) * NG + n];
            float2 p0 = make_float2(w4.x, w4.y);
            float2 p1 = make_float2(w4.z, w4.w);
            wreg[kk][0] = *(ull*)&p0;
            wreg[kk][1] = *(ull*)&p1;
        }
    }

    // ---- init hsd[0] with full h(0) (local copy from gmem) ----
    {
        int k = tid;
        hsd[0][k][0] = dupf(h_in[b0 * HID + k]);
        hsd[0][k][1] = dupf(h_in[(b0 + 1) * HID + k]);
    }

    // ---- act-thread state (tid < 64): (hl, bb) ----
    int hl = tid & 31, bb = tid >> 5;
    int n_act = (int)rank * 32 + hl;
    float creg = 0.f, hreg = 0.f;
    int slen = 0;
    if (tid < 64) {
        creg = c_in[(b0 + bb) * HID + n_act];
        hreg = h_in[(b0 + bb) * HID + n_act];
        slen = seq_lens[b0 + bb];
    }
    __syncthreads();

    float* outLL = out + (size_t)BATCH * T_LEN * AOUT;
    unsigned laddr0 = smem_u32(&hsd[0][n_act][bb]);
    unsigned laddr1 = smem_u32(&hsd[1][n_act][bb]);

#pragma unroll 1
    for (int t = 0; t < T_LEN; ++t) {
        int cur = t & 1;

        // prefetch Gx (consumed ~1000 cyc later at activation)
        float gx0 = 0.f, gx1 = 0.f, gx2 = 0.f, gx3 = 0.f;
        if (tid < 64) {
            const float* gp = g_Gx + ((size_t)(t * 32 + b0 + bb)) * NG + n_act;
            gx0 = gp[0];
            gx1 = gp[256];
            gx2 = gp[512];
            gx3 = gp[768];
        }

        // ---- h @ Wh: register weights, broadcast LDS of duplicated h ----
        ull a0 = 0, a1 = 0, a2 = 0, a3 = 0;
#pragma unroll
        for (int kk = 0; kk < 32; ++kk) {
            int k = wrp * 32 + kk;
            ulonglong2 h2 = *(const ulonglong2*)&hsd[cur][k][0];
            a0 = fma2(h2.x, wreg[kk][0], a0);
            a1 = fma2(h2.x, wreg[kk][1], a1);
            a2 = fma2(h2.y, wreg[kk][0], a2);
            a3 = fma2(h2.y, wreg[kk][1], a3);
        }
        ulonglong2 s01 = {a0, a1};
        ulonglong2 s23 = {a2, a3};
        *(ulonglong2*)&part[wrp][lane][0] = s01;
        *(ulonglong2*)&part[wrp][lane][2] = s23;
        __syncthreads();

        // ---- cross-warp k-reduction: 256 threads, one gate value each ----
        {
            int l = tid >> 3, c = (tid >> 1) & 3, h = tid & 1;
            float s = 0.f;
#pragma unroll
            for (int w = 0; w < 8; ++w)
                s += ((const float*)&part[w][l][c])[h];
            int gc = 4 * l + 2 * (c & 1) + h;
            gred[c >> 1][gc] = s;
        }
        __syncthreads();

        // ---- activations + state update + DSMEM h broadcast ----
        float outv = 0.f;
        if (tid < 64) {
            float gi = gred[bb][hl]      + gx0;
            float gj = gred[bb][32 + hl] + gx1;
            float gf = gred[bb][64 + hl] + gx2;
            float go = gred[bb][96 + hl] + gx3;
            float sf = sigm(gf + 1.f);   // FORGET_BIAS = 1
            float si = sigm(gi);
            float so = sigm(go);
            float nc = creg * sf + si * tanh_e(gj);
            float nh = tanh_e(nc) * so;
            bool mvalid = (t < slen);
            if (mvalid) { creg = nc; hreg = nh; }
            outv = mvalid ? nh : 0.f;

            ull hv = dupf(hreg);
            unsigned laddr = cur ? laddr0 : laddr1;   // write buf cur^1
#pragma unroll
            for (int pr = 0; pr < CLC; ++pr) {
                unsigned ra;
                asm volatile("mapa.shared::cluster.u32 %0, %1, %2;"
                             : "=r"(ra) : "r"(laddr), "r"(pr));
                asm volatile("st.shared::cluster.b64 [%0], %1;"
                             :: "r"(ra), "l"(hv) : "memory");
            }
        }

        asm volatile("barrier.cluster.arrive.aligned;" ::: "memory");
        // hidden behind peers' arrival:
        if (tid < 64)
            outLL[((size_t)(b0 + bb) * T_LEN + t) * HID + n_act] = outv;
        asm volatile("barrier.cluster.wait.aligned;" ::: "memory");
    }

    if (tid < 64) {   // finals
        float* cf = out + (size_t)BATCH * T_LEN * AOUT + (size_t)BATCH * T_LEN * HID;
        float* hf = cf + BATCH * HID;
        cf[(b0 + bb) * HID + n_act] = creg;
        hf[(b0 + bb) * HID + n_act] = hreg;
    }
}

// =====================================================================
// Phase 3: logits = last_layer @ W_out + b_out.
// =====================================================================
#define PROJ_TPB 288
__global__ void __launch_bounds__(PROJ_TPB) proj_kernel(const float* __restrict__ LL,
                                                        const float* __restrict__ Wo,
                                                        const float* __restrict__ bo,
                                                        float* __restrict__ logits,
                                                        int tiles_per_block) {
    __shared__ float Wsm[256 * 18];
    __shared__ float Lsm[16 * 257];

    int tid = threadIdx.x;
    for (int i = tid; i < 256 * 18; i += PROJ_TPB) Wsm[i] = Wo[i];
    int r = tid / 18;
    int a = tid - r * 18;
    float bv = bo[a];

    for (int tile = 0; tile < tiles_per_block; ++tile) {
        int rbase = (blockIdx.x * tiles_per_block + tile) * 16;
        __syncthreads();
        for (int i = tid; i < 16 * 256; i += PROJ_TPB) {
            int rr = i >> 8, c = i & 255;
            Lsm[rr * 257 + c] = LL[(size_t)rbase * 256 + i];
        }
        __syncthreads();
        float acc = 0.f;
        const float* lr = &Lsm[r * 257];
#pragma unroll 8
        for (int h = 0; h < 256; ++h)
            acc = fmaf(lr[h], Wsm[h * 18 + a], acc);
        logits[(size_t)(rbase + r) * AOUT + a] = acc + bv;
    }
}

// =====================================================================
extern "C" void kernel_launch(void* const* d_in, const int* in_sizes, int n_in,
                              void* d_out, int out_size) {
    const float* x        = (const float*)d_in[0];
    const int*   seq_lens = (const int*)  d_in[1];
    const float* c_in     = (const float*)d_in[2];
    const float* h_in     = (const float*)d_in[3];
    const float* W        = (const float*)d_in[4];
    const float* b        = (const float*)d_in[5];
    const float* W_out    = (const float*)d_in[6];
    const float* b_out    = (const float*)d_in[7];
    float* out = (float*)d_out;

    // Phase 1: input GEMM for all timesteps
    gemm_x<<<dim3(16, 512), 256>>>(x, W, b);

    // Phase 2: clustered recurrence (writes last_layer, c_fin, h_fin)
    lstm_rec<<<GBLK, 256>>>(W, seq_lens, c_in, h_in, out);

    // Phase 3: output projection (reads last_layer from out)
    const float* LL = out + (size_t)BATCH * T_LEN * AOUT;
    proj_kernel<<<512, PROJ_TPB>>>(LL, W_out, b_out, out, 8);
}